// round 1
// baseline (speedup 1.0000x reference)
#include <cuda_runtime.h>
#include <cstdint>

#define NN 50000
#define DD 64
#define EE 800000

// Scratch (no cudaMalloc allowed): 3 x 12.8 MB
__device__ float g_AGG1[NN * DD];
__device__ float g_AGG2[NN * DD];
__device__ float g_H[NN * DD];

// ---------------------------------------------------------------------------
// Zero both aggregation buffers (float4 stores, 800k threads)
// ---------------------------------------------------------------------------
__global__ __launch_bounds__(256) void zero_aggs_kernel() {
    int i = blockIdx.x * blockDim.x + threadIdx.x;
    if (i < NN * DD / 4) {
        ((float4*)g_AGG1)[i] = make_float4(0.f, 0.f, 0.f, 0.f);
        ((float4*)g_AGG2)[i] = make_float4(0.f, 0.f, 0.f, 0.f);
    }
}

// ---------------------------------------------------------------------------
// Edge scatter: agg[dst] += src_row * w.  16 lanes per edge, one float4 each.
// red.global.add.v4.f32 = 128-bit REDG (sm_90+), 4x fewer atomic ops than
// scalar atomicAdd.
// edge_index dtype is ambiguous (jnp.int64 without x64 -> int32); detect at
// runtime: if the data is int64 with values < 50000, every odd 32-bit word of
// the first 8 elements is 0.
// ---------------------------------------------------------------------------
__global__ __launch_bounds__(256) void scatter_kernel(
    const float4* __restrict__ Xv,       // [NN, 16] float4 rows
    const int*    __restrict__ ei32,     // edge_index raw words
    const float*  __restrict__ ew,
    float4*       __restrict__ agg)      // [NN, 16]
{
    int tid = blockIdx.x * blockDim.x + threadIdx.x;
    int e = tid >> 4;
    if (e >= EE) return;
    int j = tid & 15;

    bool is64 = ((ei32[1] | ei32[3] | ei32[5] | ei32[7] |
                  ei32[9] | ei32[11] | ei32[13] | ei32[15]) == 0);

    int src, dst;
    if (is64) {
        const long long* ei64 = (const long long*)ei32;
        src = (int)ei64[e];
        dst = (int)ei64[EE + e];
    } else {
        src = ei32[e];
        dst = ei32[EE + e];
    }

    float w = ew[e];
    float4 x = Xv[src * 16 + j];
    float4* p = agg + dst * 16 + j;
    asm volatile("red.global.add.v4.f32 [%0], {%1,%2,%3,%4};"
                 :: "l"(p), "f"(x.x * w), "f"(x.y * w), "f"(x.z * w), "f"(x.w * w)
                 : "memory");
}

// ---------------------------------------------------------------------------
// Fused dual-GEMM + bias + sigmoid:
//   out = sigmoid(A @ Wrel^T + R @ Wroot^T + b0 + b1 [+ b2 + b3])
// Tile: 32 rows/block, 256 threads. Each thread: column c = tid&63,
// row-group rg = tid>>6, 8 accumulators.
// W stored in smem packed as [k/4][c][4] so the per-k4 weight fetch is one
// conflict-free LDS.128; A/R row fetches are LDS.128 broadcasts (free).
// smem = 16K + 16K + 8K + 8K = 48KB exactly.
// ---------------------------------------------------------------------------
__global__ __launch_bounds__(256) void gemm_bias_sigmoid_kernel(
    const float* __restrict__ A,
    const float* __restrict__ R,
    const float* __restrict__ Wrel,   // [64,64] row-major [out][in]
    const float* __restrict__ Wroot,
    const float* __restrict__ b0, const float* __restrict__ b1,
    const float* __restrict__ b2, const float* __restrict__ b3,
    float* __restrict__ out)
{
    __shared__ float Wr[DD * DD];   // packed [kq][c][4]
    __shared__ float Wo[DD * DD];
    __shared__ float As[32 * DD];
    __shared__ float Rs[32 * DD];

    int tid = threadIdx.x;

    // Load + transpose-pack weights
    for (int i = tid; i < DD * DD; i += 256) {
        int c = i >> 6, k = i & 63;
        int di = (k >> 2) * 256 + c * 4 + (k & 3);
        Wr[di] = Wrel[i];
        Wo[di] = Wroot[i];
    }

    int row0 = blockIdx.x * 32;
    for (int i = tid; i < 32 * DD; i += 256) {
        int row = row0 + (i >> 6);
        float a = 0.f, r = 0.f;
        if (row < NN) {
            a = A[row * DD + (i & 63)];
            r = R[row * DD + (i & 63)];
        }
        As[i] = a;
        Rs[i] = r;
    }
    __syncthreads();

    int c  = tid & 63;
    int rg = tid >> 6;

    float acc[8];
#pragma unroll
    for (int r = 0; r < 8; r++) acc[r] = 0.f;

    const float4* WrQ = (const float4*)Wr;
    const float4* WoQ = (const float4*)Wo;

#pragma unroll 4
    for (int kq = 0; kq < 16; kq++) {
        float4 wr = WrQ[kq * 64 + c];
        float4 wo = WoQ[kq * 64 + c];
#pragma unroll
        for (int r = 0; r < 8; r++) {
            float4 a = *(const float4*)&As[(rg * 8 + r) * DD + kq * 4];
            float4 x = *(const float4*)&Rs[(rg * 8 + r) * DD + kq * 4];
            acc[r] += a.x * wr.x + a.y * wr.y + a.z * wr.z + a.w * wr.w
                    + x.x * wo.x + x.y * wo.y + x.z * wo.z + x.w * wo.w;
        }
    }

    float bias = b0[c] + b1[c];
    if (b2 != nullptr) bias += b2[c] + b3[c];

#pragma unroll
    for (int r = 0; r < 8; r++) {
        int row = row0 + rg * 8 + r;
        if (row < NN) {
            float v = acc[r] + bias;
            out[row * DD + c] = 1.f / (1.f + __expf(-v));
        }
    }
}

// ---------------------------------------------------------------------------
extern "C" void kernel_launch(void* const* d_in, const int* in_sizes, int n_in,
                              void* d_out, int out_size)
{
    const float* X      = (const float*)d_in[0];
    const int*   ei     = (const int*)  d_in[1];   // raw; dtype auto-detected
    const float* ew     = (const float*)d_in[2];
    const float* Wrel1  = (const float*)d_in[3];
    const float* brel1  = (const float*)d_in[4];
    const float* Wroot1 = (const float*)d_in[5];
    const float* broot1 = (const float*)d_in[6];
    const float* brel2  = (const float*)d_in[8];
    const float* broot2 = (const float*)d_in[10];
    const float* Wrel3  = (const float*)d_in[11];
    const float* brel3  = (const float*)d_in[12];
    const float* Wroot3 = (const float*)d_in[13];
    const float* broot3 = (const float*)d_in[14];
    float* out = (float*)d_out;

    float *agg1, *agg2, *h;
    cudaGetSymbolAddress((void**)&agg1, g_AGG1);
    cudaGetSymbolAddress((void**)&agg2, g_AGG2);
    cudaGetSymbolAddress((void**)&h,    g_H);

    // 1) zero both agg buffers
    zero_aggs_kernel<<<(NN * DD / 4 + 255) / 256, 256>>>();

    // 2) AGG1 = scatter(X[src]*w -> dst)
    scatter_kernel<<<(EE * 16) / 256, 256>>>((const float4*)X, ei, ew, (float4*)agg1);

    // 3) H = sigmoid(AGG1@Wrel1^T + X@Wroot1^T + brel1+broot1+brel2+broot2)
    gemm_bias_sigmoid_kernel<<<(NN + 31) / 32, 256>>>(
        agg1, X, Wrel1, Wroot1, brel1, broot1, brel2, broot2, h);

    // 4) AGG2 = scatter(H[src]*w -> dst)
    scatter_kernel<<<(EE * 16) / 256, 256>>>((const float4*)h, ei, ew, (float4*)agg2);

    // 5) out = sigmoid(AGG2@Wrel3^T + H@Wroot3^T + brel3+broot3)
    gemm_bias_sigmoid_kernel<<<(NN + 31) / 32, 256>>>(
        agg2, h, Wrel3, Wroot3, brel3, broot3, nullptr, nullptr, out);
}

// round 2
// speedup vs baseline: 1.3010x; 1.3010x over previous
#include <cuda_runtime.h>
#include <cstdint>

#define NN 50000
#define DD 64
#define EE 800000
#define SCAN_BS 1024
#define NBLK ((NN + SCAN_BS - 1) / SCAN_BS)   // 49

// Scratch (no cudaMalloc allowed)
__device__ float g_AGG[NN * DD];     // reused for both aggregation passes
__device__ float g_H[NN * DD];
__device__ int   g_counts[NN];
__device__ int   g_offsets[NN];
__device__ int   g_cursor[NN];
__device__ int   g_bsum[NBLK + 1];
__device__ int2  g_recs[EE];         // (src, bitcast(weight)) binned by dst

// ---------------------------------------------------------------------------
// edge_index dtype is ambiguous (jnp.int64 without x64 -> int32); detect at
// runtime: int64 values < 50000 have all-zero odd 32-bit words.
// ---------------------------------------------------------------------------
__device__ __forceinline__ bool detect_i64(const int* __restrict__ ei32) {
    return (ei32[1] | ei32[3] | ei32[5] | ei32[7] |
            ei32[9] | ei32[11] | ei32[13] | ei32[15]) == 0;
}
__device__ __forceinline__ void load_edge(const int* __restrict__ ei32, bool is64,
                                          int e, int& src, int& dst) {
    if (is64) {
        const long long* ei64 = (const long long*)ei32;
        src = (int)ei64[e];
        dst = (int)ei64[EE + e];
    } else {
        src = ei32[e];
        dst = ei32[EE + e];
    }
}

// ---------------------------------------------------------------------------
__global__ __launch_bounds__(256) void zero_counts_kernel() {
    int i = blockIdx.x * blockDim.x + threadIdx.x;
    if (i < NN) g_counts[i] = 0;
}

__global__ __launch_bounds__(256) void hist_kernel(const int* __restrict__ ei32) {
    int e = blockIdx.x * blockDim.x + threadIdx.x;
    if (e >= EE) return;
    bool is64 = detect_i64(ei32);
    int src, dst;
    load_edge(ei32, is64, e, src, dst);
    atomicAdd(&g_counts[dst], 1);
}

// Block-wide inclusive scan (Hillis-Steele), writes block-exclusive offsets +
// per-block totals.
__global__ __launch_bounds__(SCAN_BS) void scan1_kernel() {
    __shared__ int s[SCAN_BS];
    int i = blockIdx.x * SCAN_BS + threadIdx.x;
    int v = (i < NN) ? g_counts[i] : 0;
    s[threadIdx.x] = v;
    __syncthreads();
#pragma unroll
    for (int off = 1; off < SCAN_BS; off <<= 1) {
        int y = (threadIdx.x >= off) ? s[threadIdx.x - off] : 0;
        __syncthreads();
        s[threadIdx.x] += y;
        __syncthreads();
    }
    if (i < NN) g_offsets[i] = s[threadIdx.x] - v;   // exclusive
    if (threadIdx.x == SCAN_BS - 1) g_bsum[blockIdx.x] = s[SCAN_BS - 1];
}

__global__ void scan2_kernel() {
    // 49 values: single-thread exclusive scan (trivial)
    if (threadIdx.x == 0 && blockIdx.x == 0) {
        int run = 0;
        for (int b = 0; b < NBLK; b++) {
            int t = g_bsum[b];
            g_bsum[b] = run;
            run += t;
        }
    }
}

__global__ __launch_bounds__(256) void scan3_kernel() {
    int i = blockIdx.x * blockDim.x + threadIdx.x;
    if (i < NN) {
        int o = g_offsets[i] + g_bsum[i >> 10];
        g_offsets[i] = o;
        g_cursor[i]  = o;
    }
}

__global__ __launch_bounds__(256) void fill_kernel(const int* __restrict__ ei32,
                                                   const float* __restrict__ ew) {
    int e = blockIdx.x * blockDim.x + threadIdx.x;
    if (e >= EE) return;
    bool is64 = detect_i64(ei32);
    int src, dst;
    load_edge(ei32, is64, e, src, dst);
    int pos = atomicAdd(&g_cursor[dst], 1);
    g_recs[pos] = make_int2(src, __float_as_int(ew[e]));
}

// ---------------------------------------------------------------------------
// Gather: one warp per destination node, no atomics.
// Half-warps process edges pairwise; lane j<16 owns float4 j of the row.
// ---------------------------------------------------------------------------
__global__ __launch_bounds__(256) void gather_kernel(const float4* __restrict__ Xv,
                                                     float4* __restrict__ agg) {
    int warp = (blockIdx.x * blockDim.x + threadIdx.x) >> 5;
    if (warp >= NN) return;
    int lane = threadIdx.x & 31;
    int half = lane >> 4;
    int j    = lane & 15;

    int start = g_offsets[warp];
    int cnt   = g_counts[warp];

    float4 acc = make_float4(0.f, 0.f, 0.f, 0.f);
    for (int i = half; i < cnt; i += 2) {
        int2  rec = g_recs[start + i];          // broadcast per half-warp
        float w   = __int_as_float(rec.y);
        float4 x  = Xv[rec.x * 16 + j];         // coalesced 256B row read
        acc.x += x.x * w;
        acc.y += x.y * w;
        acc.z += x.z * w;
        acc.w += x.w * w;
    }
    acc.x += __shfl_down_sync(0xffffffffu, acc.x, 16);
    acc.y += __shfl_down_sync(0xffffffffu, acc.y, 16);
    acc.z += __shfl_down_sync(0xffffffffu, acc.z, 16);
    acc.w += __shfl_down_sync(0xffffffffu, acc.w, 16);
    if (half == 0) agg[warp * 16 + j] = acc;
}

// ---------------------------------------------------------------------------
// Fused dual-GEMM + bias + sigmoid, FFMA-bound version.
//   out = sigmoid(A @ Wrel^T + R @ Wroot^T + bias)
// 128 threads, 64-row tile. Thread (cg = tid&7, rg = tid>>3) computes
// 8 cols {cg*8+i} x 4 rows {rg*4+t}. A/R read straight from gmem (same-address
// LDG within 8 lanes coalesces to one request; no cross-warp reuse exists).
// Weights in smem with 8x8 slot transpose so per-instruction LDS addresses are
// contiguous 128B (conflict-free):  slot = kq*64 + (c&7)*8 + (c>>3).
// ---------------------------------------------------------------------------
__global__ __launch_bounds__(128) void gemm_bias_sigmoid_kernel(
    const float* __restrict__ A,
    const float* __restrict__ R,
    const float* __restrict__ Wrel,   // [64,64] row-major [out][in]
    const float* __restrict__ Wroot,
    const float* __restrict__ b0, const float* __restrict__ b1,
    const float* __restrict__ b2, const float* __restrict__ b3,
    float* __restrict__ out)
{
    __shared__ float4 WrS[16 * 64];   // 16KB
    __shared__ float4 WoS[16 * 64];

    int tid = threadIdx.x;
    const float4* Wrel4  = (const float4*)Wrel;
    const float4* Wroot4 = (const float4*)Wroot;
    for (int idx = tid; idx < 1024; idx += 128) {
        int c = idx >> 4, kq = idx & 15;
        int slot = kq * 64 + (c & 7) * 8 + (c >> 3);
        WrS[slot] = Wrel4[idx];
        WoS[slot] = Wroot4[idx];
    }
    __syncthreads();

    int cg = tid & 7;
    int rg = tid >> 3;
    int row0 = blockIdx.x * 64 + rg * 4;

    float acc[8][4];
#pragma unroll
    for (int i = 0; i < 8; i++)
#pragma unroll
        for (int t = 0; t < 4; t++) acc[i][t] = 0.f;

    const float4* A4 = (const float4*)A;
    const float4* R4 = (const float4*)R;
    bool full = (row0 + 3 < NN);

#pragma unroll 2
    for (int kq = 0; kq < 16; kq++) {
        float4 a[4], r[4];
#pragma unroll
        for (int t = 0; t < 4; t++) {
            int row = row0 + t;
            if (full || row < NN) {
                a[t] = A4[row * 16 + kq];
                r[t] = R4[row * 16 + kq];
            } else {
                a[t] = make_float4(0.f, 0.f, 0.f, 0.f);
                r[t] = make_float4(0.f, 0.f, 0.f, 0.f);
            }
        }
#pragma unroll
        for (int i = 0; i < 8; i++) {
            float4 wr = WrS[kq * 64 + i * 8 + cg];   // lanes cg=0..7 contiguous
            float4 wo = WoS[kq * 64 + i * 8 + cg];
#pragma unroll
            for (int t = 0; t < 4; t++) {
                acc[i][t] += a[t].x * wr.x + a[t].y * wr.y
                           + a[t].z * wr.z + a[t].w * wr.w
                           + r[t].x * wo.x + r[t].y * wo.y
                           + r[t].z * wo.z + r[t].w * wo.w;
            }
        }
    }

    float bias[8];
#pragma unroll
    for (int i = 0; i < 8; i++) {
        int c = cg * 8 + i;
        bias[i] = b0[c] + b1[c];
        if (b2 != nullptr) bias[i] += b2[c] + b3[c];
    }

#pragma unroll
    for (int t = 0; t < 4; t++) {
        int row = row0 + t;
        if (row < NN) {
            float4 o0, o1;
            o0.x = 1.f / (1.f + __expf(-(acc[0][t] + bias[0])));
            o0.y = 1.f / (1.f + __expf(-(acc[1][t] + bias[1])));
            o0.z = 1.f / (1.f + __expf(-(acc[2][t] + bias[2])));
            o0.w = 1.f / (1.f + __expf(-(acc[3][t] + bias[3])));
            o1.x = 1.f / (1.f + __expf(-(acc[4][t] + bias[4])));
            o1.y = 1.f / (1.f + __expf(-(acc[5][t] + bias[5])));
            o1.z = 1.f / (1.f + __expf(-(acc[6][t] + bias[6])));
            o1.w = 1.f / (1.f + __expf(-(acc[7][t] + bias[7])));
            float4* op = (float4*)&out[row * DD + cg * 8];
            op[0] = o0;
            op[1] = o1;
        }
    }
}

// ---------------------------------------------------------------------------
extern "C" void kernel_launch(void* const* d_in, const int* in_sizes, int n_in,
                              void* d_out, int out_size)
{
    const float* X      = (const float*)d_in[0];
    const int*   ei     = (const int*)  d_in[1];   // raw; dtype auto-detected
    const float* ew     = (const float*)d_in[2];
    const float* Wrel1  = (const float*)d_in[3];
    const float* brel1  = (const float*)d_in[4];
    const float* Wroot1 = (const float*)d_in[5];
    const float* broot1 = (const float*)d_in[6];
    const float* brel2  = (const float*)d_in[8];
    const float* broot2 = (const float*)d_in[10];
    const float* Wrel3  = (const float*)d_in[11];
    const float* brel3  = (const float*)d_in[12];
    const float* Wroot3 = (const float*)d_in[13];
    const float* broot3 = (const float*)d_in[14];
    float* out = (float*)d_out;

    float *agg, *h;
    cudaGetSymbolAddress((void**)&agg, g_AGG);
    cudaGetSymbolAddress((void**)&h,   g_H);

    // --- CSR build (once; shared by both aggregation passes) ---
    zero_counts_kernel<<<(NN + 255) / 256, 256>>>();
    hist_kernel<<<(EE + 255) / 256, 256>>>(ei);
    scan1_kernel<<<NBLK, SCAN_BS>>>();
    scan2_kernel<<<1, 32>>>();
    scan3_kernel<<<(NN + 255) / 256, 256>>>();
    fill_kernel<<<(EE + 255) / 256, 256>>>(ei, ew);

    // --- pass 1: AGG = scatter(X[src]*w -> dst), atomic-free gather ---
    gather_kernel<<<(NN * 32 + 255) / 256, 256>>>((const float4*)X, (float4*)agg);

    // H = sigmoid(AGG@Wrel1^T + X@Wroot1^T + brel1+broot1+brel2+broot2)
    gemm_bias_sigmoid_kernel<<<(NN + 63) / 64, 128>>>(
        agg, X, Wrel1, Wroot1, brel1, broot1, brel2, broot2, h);

    // --- pass 2: AGG = scatter(H[src]*w -> dst) ---
    gather_kernel<<<(NN * 32 + 255) / 256, 256>>>((const float4*)h, (float4*)agg);

    // out = sigmoid(AGG@Wrel3^T + H@Wroot3^T + brel3+broot3)
    gemm_bias_sigmoid_kernel<<<(NN + 63) / 64, 128>>>(
        agg, h, Wrel3, Wroot3, brel3, broot3, nullptr, nullptr, out);
}